// round 15
// baseline (speedup 1.0000x reference)
#include <cuda_runtime.h>
#include <cuda_fp16.h>
#include <cstdint>

// Problem constants
#define BATCH     4
#define SEQ       1024
#define EMB       1024
#define NHEADS    16
#define HDIM      64
#define QKV_COLS  (3 * NHEADS * HDIM)   // 3072
#define ROWS      (BATCH * SEQ)         // 4096

// Scratch (allocation-free rule: __device__ globals)
__device__ __half g_qkv[ROWS * QKV_COLS];   // fp16 QKV (GEMM1 out)
__device__ __half g_att[ROWS * EMB];        // fp16 attention out
__device__ __half g_xh[ROWS * EMB];         // fp16 x
__device__ __half g_wqkvh[EMB * QKV_COLS];  // fp16 W_qkv [K][N]
__device__ __half g_wouth[EMB * EMB];       // fp16 W_out [K][N]

// ---------------------------------------------------------------------------
// Helpers
// ---------------------------------------------------------------------------
__device__ __forceinline__ void mma_f16(float c[4], const uint32_t a[4], const uint32_t b[2]) {
    asm volatile(
        "mma.sync.aligned.m16n8k16.row.col.f32.f16.f16.f32 "
        "{%0,%1,%2,%3},{%4,%5,%6,%7},{%8,%9},{%0,%1,%2,%3};"
        : "+f"(c[0]), "+f"(c[1]), "+f"(c[2]), "+f"(c[3])
        : "r"(a[0]), "r"(a[1]), "r"(a[2]), "r"(a[3]), "r"(b[0]), "r"(b[1]));
}
__device__ __forceinline__ void ldsm_x4(uint32_t& r0, uint32_t& r1,
                                        uint32_t& r2, uint32_t& r3, uint32_t addr) {
    asm volatile("ldmatrix.sync.aligned.m8n8.x4.shared.b16 {%0,%1,%2,%3}, [%4];"
                 : "=r"(r0), "=r"(r1), "=r"(r2), "=r"(r3) : "r"(addr));
}
__device__ __forceinline__ void ldsm_x4t(uint32_t& r0, uint32_t& r1,
                                         uint32_t& r2, uint32_t& r3, uint32_t addr) {
    asm volatile("ldmatrix.sync.aligned.m8n8.x4.trans.shared.b16 {%0,%1,%2,%3}, [%4];"
                 : "=r"(r0), "=r"(r1), "=r"(r2), "=r"(r3) : "r"(addr));
}
// pack two fp32 -> fp16x2 (lo = first arg)
__device__ __forceinline__ uint32_t pack_h2(float lo, float hi) {
    uint32_t r;
    asm("cvt.rn.f16x2.f32 %0, %1, %2;" : "=r"(r) : "f"(hi), "f"(lo));
    return r;
}
__device__ __forceinline__ void cp_async16(uint32_t dst, const void* src) {
    asm volatile("cp.async.cg.shared.global [%0], [%1], 16;" :: "r"(dst), "l"(src));
}
__device__ __forceinline__ void cp_commit() {
    asm volatile("cp.async.commit_group;");
}
template <int N>
__device__ __forceinline__ void cp_wait() {
    asm volatile("cp.async.wait_group %0;" :: "n"(N));
}

// ---------------------------------------------------------------------------
// Prepass: fp32 -> fp16 convert, 3 tensors in ONE launch (grid-stride)
// ---------------------------------------------------------------------------
__global__ void f2h3(const float2* __restrict__ s0, __half2* __restrict__ d0, int n0,
                     const float2* __restrict__ s1, __half2* __restrict__ d1, int n1,
                     const float2* __restrict__ s2, __half2* __restrict__ d2, int n2)
{
    const int total = n0 + n1 + n2;
    for (int i = blockIdx.x * blockDim.x + threadIdx.x; i < total;
         i += gridDim.x * blockDim.x) {
        const float2* s; __half2* d; int j = i;
        if (j < n0)              { s = s0; d = d0; }
        else if ((j -= n0) < n1) { s = s1; d = d1; }
        else                     { j -= n1; s = s2; d = d2; }
        float2 v = s[j];
        d[j] = __floats2half2_rn(v.x, v.y);
    }
}

// ===========================================================================
// fp16 m16n8k16 GEMM, fused bias (R11 shape, STG=4 pipeline):
// CTA 128x128x32, 8 warps (2x4), warp tile 64x32.
// A [M][K], B [K][N]; A frags ldmatrix.x4, B frags ldmatrix.x4.trans.
// SA=56h, SB=136h (conflict-free ldmatrix wavefronts).
// 4-stage cp.async (two fills in flight), one __syncthreads/iter, 2 CTAs/SM.
// ===========================================================================
#define GBM 128
#define GBN 128
#define GBK 32
#define STG 4
#define SA  56
#define SB  136
#define ABUFH (128 * SA)                  // 7168 halves
#define BBUFH (32 * SB)                   // 4352 halves
#define GEMM_SMEM (STG * (ABUFH + BBUFH) * 2)   // 92160 bytes

template <bool OUT32>
__global__ __launch_bounds__(256, 2) void hgemm_bias(
    int M, int N, int K,
    const __half* __restrict__ A,
    const __half* __restrict__ B,
    const float* __restrict__ bias,
    void* __restrict__ Cout)
{
    extern __shared__ __half smh[];
    __half* As = smh;
    __half* Bs = smh + STG * ABUFH;
    const uint32_t sA = (uint32_t)__cvta_generic_to_shared(As);
    const uint32_t sB = (uint32_t)__cvta_generic_to_shared(Bs);

    const int t    = threadIdx.x;
    const int lane = t & 31;
    const int warp = t >> 5;
    const int wm   = warp >> 2;   // 0..1
    const int wn   = warp & 3;    // 0..3
    const int grp  = lane >> 2;
    const int qid  = lane & 3;
    const int mm   = lane >> 3;   // ldmatrix matrix id 0..3
    const int rr   = lane & 7;

    const uint32_t aL = (uint32_t)((rr + 8 * (mm & 1)) * SA + 8 * (mm >> 1));
    const uint32_t bL = (uint32_t)((rr + 8 * (mm & 1)) * SB + 8 * (mm >> 1));

    const int bm = blockIdx.y * GBM;
    const int bn = blockIdx.x * GBN;

    // staging: A 128 rows x 64B (2 thr/row, 2x16B); B 32 rows x 256B (8 thr/row, 2x16B)
    const int srowA = t >> 1, ssegA = (t & 1) * 2;
    const int srowB = t >> 3, ssegB = (t & 7) * 2;

    auto issue = [&](int buf, int kt) {
        const __half* Ag = A + (size_t)(bm + srowA) * K + kt * GBK;
        #pragma unroll
        for (int s = 0; s < 2; s++) {
            int seg = ssegA + s;
            cp_async16(sA + (uint32_t)(buf * ABUFH + srowA * SA + seg * 8) * 2,
                       Ag + seg * 8);
        }
        const __half* Bg = B + (size_t)(kt * GBK + srowB) * N + bn;
        #pragma unroll
        for (int s = 0; s < 2; s++) {
            int seg = ssegB + s;
            cp_async16(sB + (uint32_t)(buf * BBUFH + srowB * SB + seg * 8) * 2,
                       Bg + seg * 8);
        }
    };

    float c[4][4][4];
    #pragma unroll
    for (int mi = 0; mi < 4; mi++)
        #pragma unroll
        for (int ni = 0; ni < 4; ni++)
            #pragma unroll
            for (int r = 0; r < 4; r++)
                c[mi][ni][r] = 0.0f;

    issue(0, 0); cp_commit();
    issue(1, 1); cp_commit();
    issue(2, 2); cp_commit();

    const int NT = K / GBK;
    for (int kt = 0; kt < NT; kt++) {
        if (kt + STG - 1 < NT) cp_wait<STG - 2>();
        else                   cp_wait<0>();
        __syncthreads();

        if (kt + STG - 1 < NT) {
            issue((kt + STG - 1) % STG, kt + STG - 1);
            cp_commit();
        }

        const int cur = kt % STG;
        const uint32_t aw = sA + (uint32_t)(cur * ABUFH + wm * 64 * SA + aL) * 2;
        const uint32_t bw = sB + (uint32_t)(cur * BBUFH + wn * 32 + bL) * 2;

        #pragma unroll
        for (int ks = 0; ks < 2; ks++) {
            uint32_t af[4][4], bf[4][2];
            #pragma unroll
            for (int mi = 0; mi < 4; mi++)
                ldsm_x4(af[mi][0], af[mi][1], af[mi][2], af[mi][3],
                        aw + (uint32_t)(mi * 16 * SA + ks * 16) * 2);
            #pragma unroll
            for (int ni2 = 0; ni2 < 2; ni2++)
                ldsm_x4t(bf[2 * ni2][0], bf[2 * ni2][1],
                         bf[2 * ni2 + 1][0], bf[2 * ni2 + 1][1],
                         bw + (uint32_t)(ks * 16 * SB + ni2 * 16) * 2);
            #pragma unroll
            for (int mi = 0; mi < 4; mi++)
                #pragma unroll
                for (int ni = 0; ni < 4; ni++)
                    mma_f16(c[mi][ni], af[mi], bf[ni]);
        }
    }
    __syncthreads();

    // epilogue
    #pragma unroll
    for (int mi = 0; mi < 4; mi++) {
        const int r0 = bm + wm * 64 + mi * 16 + grp;
        #pragma unroll
        for (int ni = 0; ni < 4; ni++) {
            const int col = bn + wn * 32 + ni * 8 + qid * 2;
            float2 bv = *(const float2*)&bias[col];
            float x0 = c[mi][ni][0] + bv.x, x1 = c[mi][ni][1] + bv.y;
            float x2 = c[mi][ni][2] + bv.x, x3 = c[mi][ni][3] + bv.y;
            if (OUT32) {
                float* C = (float*)Cout;
                *(float2*)&C[(size_t)r0 * N + col]       = make_float2(x0, x1);
                *(float2*)&C[(size_t)(r0 + 8) * N + col] = make_float2(x2, x3);
            } else {
                __half* C = (__half*)Cout;
                *(uint32_t*)&C[(size_t)r0 * N + col]       = pack_h2(x0, x1);
                *(uint32_t*)&C[(size_t)(r0 + 8) * N + col] = pack_h2(x2, x3);
            }
        }
    }
}

// ===========================================================================
// fp16 flash attention: O = softmax(QK^T/8)V per (b,h).
// 128-key SUPER-TILES, double-buffered cp.async (issue kt+1 before compute
// of kt -> full fill/compute overlap; 8 syncs total). Compute processes two
// 64-key halves per tile with the validated R14 fragment code (registers
// unchanged). P stays in registers between QK and PV.
// ===========================================================================
#define KSTR 72
#define KVBUF2 (128 * KSTR)               // halves per 128-key K (or V) buffer
#define ATT_SMEM ((2 * 2 * KVBUF2 + 128 * KSTR) * 2)   // 92160 bytes

__global__ __launch_bounds__(256, 2) void attn_f16_kernel()
{
    extern __shared__ __half sma[];
    __half* Qsm = sma + 4 * KVBUF2;       // [128][KSTR]
    const uint32_t sKbase = (uint32_t)__cvta_generic_to_shared(sma);
    const uint32_t sVbase = sKbase + (uint32_t)(2 * KVBUF2) * 2;
    const uint32_t sQ     = sKbase + (uint32_t)(4 * KVBUF2) * 2;

    const int t    = threadIdx.x;
    const int lane = t & 31;
    const int warp = t >> 5;
    const int grp  = lane >> 2;
    const int qid  = lane & 3;
    const int mm   = lane >> 3;
    const int rr   = lane & 7;

    const int bh = blockIdx.y;
    const int b  = bh >> 4;
    const int h  = bh & 15;
    const int hoff  = h * HDIM;
    const int qrow0 = blockIdx.x * 128;

    const int rowStride = QKV_COLS;
    const __half* Kg = g_qkv + (size_t)b * SEQ * rowStride + hoff;           // K third
    const __half* Vg = Kg + 2 * EMB;                                         // V third
    const __half* Qg = g_qkv + ((size_t)b * SEQ + qrow0) * rowStride + EMB + hoff;

    // K/V staging (128 rows x 128B per buffer): 2 thr/row, 4x16B each
    const int kvrow = t >> 1;
    const int kvs0  = (t & 1) * 4;

    auto issue_kv = [&](int buf, int kt) {
        const __half* Kn = Kg + (size_t)kt * 128 * rowStride;
        const __half* Vn = Vg + (size_t)kt * 128 * rowStride;
        #pragma unroll
        for (int s = 0; s < 4; s++) {
            int seg = kvs0 + s;
            uint32_t off = (uint32_t)(buf * KVBUF2 + kvrow * KSTR + seg * 8) * 2;
            cp_async16(sKbase + off, Kn + (size_t)kvrow * rowStride + seg * 8);
            cp_async16(sVbase + off, Vn + (size_t)kvrow * rowStride + seg * 8);
        }
    };

    // ---- stage Q synchronously: 128 rows x 128B; 2 thr/row, 4x16B each ----
    {
        const int j  = t >> 1;
        const int s0 = (t & 1) * 4;
        #pragma unroll
        for (int p = 0; p < 4; p++) {
            int seg = s0 + p;
            *(uint4*)&Qsm[j * KSTR + seg * 8] =
                *(const uint4*)&Qg[(size_t)j * rowStride + seg * 8];
        }
    }
    // prologue: stage 0
    issue_kv(0, 0); cp_commit();
    __syncthreads();

    // ---- Q fragments (held in registers) ----
    uint32_t qa[4][4];
    {
        const uint32_t qw = sQ +
            (uint32_t)((warp * 16 + rr + 8 * (mm & 1)) * KSTR + 8 * (mm >> 1)) * 2;
        #pragma unroll
        for (int ks = 0; ks < 4; ks++)
            ldsm_x4(qa[ks][0], qa[ks][1], qa[ks][2], qa[ks][3],
                    qw + (uint32_t)(ks * 16) * 2);
    }

    float oc[8][4];
    #pragma unroll
    for (int ni = 0; ni < 8; ni++)
        #pragma unroll
        for (int r = 0; r < 4; r++) oc[ni][r] = 0.0f;
    float lsum0 = 0.0f, lsum1 = 0.0f;

    const uint32_t kL = (uint32_t)((rr + 8 * (mm >> 1)) * KSTR + 8 * (mm & 1));
    const uint32_t vL = (uint32_t)((rr + 8 * (mm & 1)) * KSTR + 8 * (mm >> 1));

    const int NKT = SEQ / 128;   // 8
    for (int kt = 0; kt < NKT; kt++) {
        cp_wait<0>();            // stage kt landed (only group pending)
        __syncthreads();

        if (kt + 1 < NKT) {      // fill other buffer while computing this one
            issue_kv((kt + 1) & 1, kt + 1);
            cp_commit();
        }

        #pragma unroll
        for (int half = 0; half < 2; half++) {
            const uint32_t sKb = sKbase +
                (uint32_t)((kt & 1) * KVBUF2 + half * 64 * KSTR) * 2;
            const uint32_t sVb = sVbase +
                (uint32_t)((kt & 1) * KVBUF2 + half * 64 * KSTR) * 2;

            // ---- S = Q K^T ----
            float sc[8][4];
            #pragma unroll
            for (int ni = 0; ni < 8; ni++)
                #pragma unroll
                for (int r = 0; r < 4; r++) sc[ni][r] = 0.0f;

            #pragma unroll
            for (int ks = 0; ks < 4; ks++) {
                uint32_t bf[8][2];
                #pragma unroll
                for (int ni2 = 0; ni2 < 4; ni2++)
                    ldsm_x4(bf[2 * ni2][0], bf[2 * ni2][1],
                            bf[2 * ni2 + 1][0], bf[2 * ni2 + 1][1],
                            sKb + (uint32_t)(ni2 * 16 * KSTR + ks * 16 + kL) * 2);
                #pragma unroll
                for (int ni = 0; ni < 8; ni++)
                    mma_f16(sc[ni], qa[ks], bf[ni]);
            }

            // ---- P = exp(S/8); row sums ----
            #pragma unroll
            for (int ni = 0; ni < 8; ni++) {
                sc[ni][0] = __expf(sc[ni][0] * 0.125f);
                sc[ni][1] = __expf(sc[ni][1] * 0.125f);
                sc[ni][2] = __expf(sc[ni][2] * 0.125f);
                sc[ni][3] = __expf(sc[ni][3] * 0.125f);
                lsum0 += sc[ni][0] + sc[ni][1];
                lsum1 += sc[ni][2] + sc[ni][3];
            }

            // ---- O += P V (P packed from registers) ----
            #pragma unroll
            for (int ks = 0; ks < 4; ks++) {
                uint32_t af[4];
                af[0] = pack_h2(sc[2 * ks][0],     sc[2 * ks][1]);
                af[1] = pack_h2(sc[2 * ks][2],     sc[2 * ks][3]);
                af[2] = pack_h2(sc[2 * ks + 1][0], sc[2 * ks + 1][1]);
                af[3] = pack_h2(sc[2 * ks + 1][2], sc[2 * ks + 1][3]);
                uint32_t bf[8][2];
                #pragma unroll
                for (int ni2 = 0; ni2 < 4; ni2++)
                    ldsm_x4t(bf[2 * ni2][0], bf[2 * ni2][1],
                             bf[2 * ni2 + 1][0], bf[2 * ni2 + 1][1],
                             sVb + (uint32_t)(ks * 16 * KSTR + ni2 * 16 + vL) * 2);
                #pragma unroll
                for (int ni = 0; ni < 8; ni++)
                    mma_f16(oc[ni], af, bf[ni]);
            }
        }
    }

    // ---- normalize, write fp16 ----
    float l0 = lsum0, l1 = lsum1;
    #pragma unroll
    for (int m = 1; m < 4; m <<= 1) {
        l0 += __shfl_xor_sync(0xffffffffu, l0, m);
        l1 += __shfl_xor_sync(0xffffffffu, l1, m);
    }
    const float inv0 = 1.0f / l0;
    const float inv1 = 1.0f / l1;

    const int r0 = qrow0 + warp * 16 + grp;
    __half* O0 = g_att + ((size_t)b * SEQ + r0) * EMB + hoff;
    __half* O1 = O0 + 8 * EMB;
    #pragma unroll
    for (int ni = 0; ni < 8; ni++) {
        const int col = ni * 8 + qid * 2;
        *(uint32_t*)&O0[col] = pack_h2(oc[ni][0] * inv0, oc[ni][1] * inv0);
        *(uint32_t*)&O1[col] = pack_h2(oc[ni][2] * inv1, oc[ni][3] * inv1);
    }
}

// ---------------------------------------------------------------------------
// Launch: inputs in order x, W_qkv, b_qkv, W_out, b_out
// ---------------------------------------------------------------------------
extern "C" void kernel_launch(void* const* d_in, const int* in_sizes, int n_in,
                              void* d_out, int out_size)
{
    const float* x     = (const float*)d_in[0];
    const float* W_qkv = (const float*)d_in[1];
    const float* b_qkv = (const float*)d_in[2];
    const float* W_out = (const float*)d_in[3];
    const float* b_out = (const float*)d_in[4];
    float*       out   = (float*)d_out;

    __half *qkv_p, *att_p, *xh_p, *wq_p, *wo_p;
    cudaGetSymbolAddress((void**)&qkv_p, g_qkv);
    cudaGetSymbolAddress((void**)&att_p, g_att);
    cudaGetSymbolAddress((void**)&xh_p,  g_xh);
    cudaGetSymbolAddress((void**)&wq_p,  g_wqkvh);
    cudaGetSymbolAddress((void**)&wo_p,  g_wouth);

    static bool attr_set = false;
    if (!attr_set) {
        cudaFuncSetAttribute(hgemm_bias<false>,
                             cudaFuncAttributeMaxDynamicSharedMemorySize, GEMM_SMEM);
        cudaFuncSetAttribute(hgemm_bias<true>,
                             cudaFuncAttributeMaxDynamicSharedMemorySize, GEMM_SMEM);
        cudaFuncSetAttribute(attn_f16_kernel,
                             cudaFuncAttributeMaxDynamicSharedMemorySize, ATT_SMEM);
        attr_set = true;
    }

    // 0) fp32 -> fp16 prepass (one launch for all three tensors)
    f2h3<<<1024, 256>>>(
        (const float2*)x,     (__half2*)xh_p, ROWS * EMB / 2,
        (const float2*)W_qkv, (__half2*)wq_p, EMB * QKV_COLS / 2,
        (const float2*)W_out, (__half2*)wo_p, EMB * EMB / 2);

    // 1) QKV projection -> fp16
    {
        dim3 grid(QKV_COLS / GBN, ROWS / GBM);   // (24, 32)
        hgemm_bias<false><<<grid, 256, GEMM_SMEM>>>(
            ROWS, QKV_COLS, EMB, xh_p, wq_p, b_qkv, qkv_p);
    }

    // 2) Attention -> fp16
    {
        dim3 grid(SEQ / 128, BATCH * NHEADS);    // (8, 64)
        attn_f16_kernel<<<grid, 256, ATT_SMEM>>>();
    }

    // 3) Output projection -> fp32
    {
        dim3 grid(EMB / GBN, ROWS / GBM);        // (8, 32)
        hgemm_bias<true><<<grid, 256, GEMM_SMEM>>>(
            ROWS, EMB, EMB, att_p, wo_p, b_out, out);
    }
}

// round 16
// speedup vs baseline: 1.0597x; 1.0597x over previous
#include <cuda_runtime.h>
#include <cuda_fp16.h>
#include <cstdint>

// Problem constants
#define BATCH     4
#define SEQ       1024
#define EMB       1024
#define NHEADS    16
#define HDIM      64
#define QKV_COLS  (3 * NHEADS * HDIM)   // 3072
#define ROWS      (BATCH * SEQ)         // 4096

// Scratch (allocation-free rule: __device__ globals)
__device__ __half g_qkv[ROWS * QKV_COLS];   // fp16 QKV (GEMM1 out)
__device__ __half g_att[ROWS * EMB];        // fp16 attention out
__device__ __half g_xh[ROWS * EMB];         // fp16 x
__device__ __half g_wqkvh[EMB * QKV_COLS];  // fp16 W_qkv [K][N]
__device__ __half g_wouth[EMB * EMB];       // fp16 W_out [K][N]

// ---------------------------------------------------------------------------
// Helpers
// ---------------------------------------------------------------------------
__device__ __forceinline__ void mma_f16(float c[4], const uint32_t a[4], const uint32_t b[2]) {
    asm volatile(
        "mma.sync.aligned.m16n8k16.row.col.f32.f16.f16.f32 "
        "{%0,%1,%2,%3},{%4,%5,%6,%7},{%8,%9},{%0,%1,%2,%3};"
        : "+f"(c[0]), "+f"(c[1]), "+f"(c[2]), "+f"(c[3])
        : "r"(a[0]), "r"(a[1]), "r"(a[2]), "r"(a[3]), "r"(b[0]), "r"(b[1]));
}
__device__ __forceinline__ void ldsm_x4(uint32_t& r0, uint32_t& r1,
                                        uint32_t& r2, uint32_t& r3, uint32_t addr) {
    asm volatile("ldmatrix.sync.aligned.m8n8.x4.shared.b16 {%0,%1,%2,%3}, [%4];"
                 : "=r"(r0), "=r"(r1), "=r"(r2), "=r"(r3) : "r"(addr));
}
__device__ __forceinline__ void ldsm_x4t(uint32_t& r0, uint32_t& r1,
                                         uint32_t& r2, uint32_t& r3, uint32_t addr) {
    asm volatile("ldmatrix.sync.aligned.m8n8.x4.trans.shared.b16 {%0,%1,%2,%3}, [%4];"
                 : "=r"(r0), "=r"(r1), "=r"(r2), "=r"(r3) : "r"(addr));
}
// pack two fp32 -> fp16x2 (lo = first arg)
__device__ __forceinline__ uint32_t pack_h2(float lo, float hi) {
    uint32_t r;
    asm("cvt.rn.f16x2.f32 %0, %1, %2;" : "=r"(r) : "f"(hi), "f"(lo));
    return r;
}
__device__ __forceinline__ void cp_async16(uint32_t dst, const void* src) {
    asm volatile("cp.async.cg.shared.global [%0], [%1], 16;" :: "r"(dst), "l"(src));
}
__device__ __forceinline__ void cp_commit() {
    asm volatile("cp.async.commit_group;");
}
template <int N>
__device__ __forceinline__ void cp_wait() {
    asm volatile("cp.async.wait_group %0;" :: "n"(N));
}

// ---------------------------------------------------------------------------
// Prepass: fp32 -> fp16 convert, 3 tensors in ONE launch (grid-stride)
// ---------------------------------------------------------------------------
__global__ void f2h3(const float2* __restrict__ s0, __half2* __restrict__ d0, int n0,
                     const float2* __restrict__ s1, __half2* __restrict__ d1, int n1,
                     const float2* __restrict__ s2, __half2* __restrict__ d2, int n2)
{
    const int total = n0 + n1 + n2;
    for (int i = blockIdx.x * blockDim.x + threadIdx.x; i < total;
         i += gridDim.x * blockDim.x) {
        const float2* s; __half2* d; int j = i;
        if (j < n0)              { s = s0; d = d0; }
        else if ((j -= n0) < n1) { s = s1; d = d1; }
        else                     { j -= n1; s = s2; d = d2; }
        float2 v = s[j];
        d[j] = __floats2half2_rn(v.x, v.y);
    }
}

// ===========================================================================
// fp16 m16n8k16 GEMM, fused bias (R14 config — best measured):
// CTA 128x128x32, 8 warps (2x4), warp tile 64x32.
// A [M][K], B [K][N]; A frags ldmatrix.x4, B frags ldmatrix.x4.trans.
// SA=56h, SB=136h (conflict-free ldmatrix wavefronts).
// 3-stage cp.async, one __syncthreads per iter, 2 CTAs/SM.
// Epilogue: bias loads hoisted out of the mi-loop.
// ===========================================================================
#define GBM 128
#define GBN 128
#define GBK 32
#define STG 3
#define SA  56
#define SB  136
#define ABUFH (128 * SA)                  // 7168 halves
#define BBUFH (32 * SB)                   // 4352 halves
#define GEMM_SMEM (STG * (ABUFH + BBUFH) * 2)   // 69120 bytes

template <bool OUT32>
__global__ __launch_bounds__(256, 2) void hgemm_bias(
    int M, int N, int K,
    const __half* __restrict__ A,
    const __half* __restrict__ B,
    const float* __restrict__ bias,
    void* __restrict__ Cout)
{
    extern __shared__ __half smh[];
    __half* As = smh;
    __half* Bs = smh + STG * ABUFH;
    const uint32_t sA = (uint32_t)__cvta_generic_to_shared(As);
    const uint32_t sB = (uint32_t)__cvta_generic_to_shared(Bs);

    const int t    = threadIdx.x;
    const int lane = t & 31;
    const int warp = t >> 5;
    const int wm   = warp >> 2;   // 0..1
    const int wn   = warp & 3;    // 0..3
    const int grp  = lane >> 2;
    const int qid  = lane & 3;
    const int mm   = lane >> 3;   // ldmatrix matrix id 0..3
    const int rr   = lane & 7;

    const uint32_t aL = (uint32_t)((rr + 8 * (mm & 1)) * SA + 8 * (mm >> 1));
    const uint32_t bL = (uint32_t)((rr + 8 * (mm & 1)) * SB + 8 * (mm >> 1));

    const int bm = blockIdx.y * GBM;
    const int bn = blockIdx.x * GBN;

    // staging: A 128 rows x 64B (2 thr/row, 2x16B); B 32 rows x 256B (8 thr/row, 2x16B)
    const int srowA = t >> 1, ssegA = (t & 1) * 2;
    const int srowB = t >> 3, ssegB = (t & 7) * 2;

    auto issue = [&](int buf, int kt) {
        const __half* Ag = A + (size_t)(bm + srowA) * K + kt * GBK;
        #pragma unroll
        for (int s = 0; s < 2; s++) {
            int seg = ssegA + s;
            cp_async16(sA + (uint32_t)(buf * ABUFH + srowA * SA + seg * 8) * 2,
                       Ag + seg * 8);
        }
        const __half* Bg = B + (size_t)(kt * GBK + srowB) * N + bn;
        #pragma unroll
        for (int s = 0; s < 2; s++) {
            int seg = ssegB + s;
            cp_async16(sB + (uint32_t)(buf * BBUFH + srowB * SB + seg * 8) * 2,
                       Bg + seg * 8);
        }
    };

    float c[4][4][4];
    #pragma unroll
    for (int mi = 0; mi < 4; mi++)
        #pragma unroll
        for (int ni = 0; ni < 4; ni++)
            #pragma unroll
            for (int r = 0; r < 4; r++)
                c[mi][ni][r] = 0.0f;

    issue(0, 0); cp_commit();
    issue(1, 1); cp_commit();

    const int NT = K / GBK;
    for (int kt = 0; kt < NT; kt++) {
        if (kt + STG - 1 < NT) cp_wait<STG - 2>();
        else                   cp_wait<0>();
        __syncthreads();

        if (kt + STG - 1 < NT) {
            issue((kt + STG - 1) % STG, kt + STG - 1);
            cp_commit();
        }

        const int cur = kt % STG;
        const uint32_t aw = sA + (uint32_t)(cur * ABUFH + wm * 64 * SA + aL) * 2;
        const uint32_t bw = sB + (uint32_t)(cur * BBUFH + wn * 32 + bL) * 2;

        #pragma unroll
        for (int ks = 0; ks < 2; ks++) {
            uint32_t af[4][4], bf[4][2];
            #pragma unroll
            for (int mi = 0; mi < 4; mi++)
                ldsm_x4(af[mi][0], af[mi][1], af[mi][2], af[mi][3],
                        aw + (uint32_t)(mi * 16 * SA + ks * 16) * 2);
            #pragma unroll
            for (int ni2 = 0; ni2 < 2; ni2++)
                ldsm_x4t(bf[2 * ni2][0], bf[2 * ni2][1],
                         bf[2 * ni2 + 1][0], bf[2 * ni2 + 1][1],
                         bw + (uint32_t)(ks * 16 * SB + ni2 * 16) * 2);
            #pragma unroll
            for (int mi = 0; mi < 4; mi++)
                #pragma unroll
                for (int ni = 0; ni < 4; ni++)
                    mma_f16(c[mi][ni], af[mi], bf[ni]);
        }
    }
    __syncthreads();

    // epilogue: bias hoisted (same 4 values reused across all mi)
    float2 bv[4];
    #pragma unroll
    for (int ni = 0; ni < 4; ni++)
        bv[ni] = *(const float2*)&bias[bn + wn * 32 + ni * 8 + qid * 2];

    #pragma unroll
    for (int mi = 0; mi < 4; mi++) {
        const int r0 = bm + wm * 64 + mi * 16 + grp;
        #pragma unroll
        for (int ni = 0; ni < 4; ni++) {
            const int col = bn + wn * 32 + ni * 8 + qid * 2;
            float x0 = c[mi][ni][0] + bv[ni].x, x1 = c[mi][ni][1] + bv[ni].y;
            float x2 = c[mi][ni][2] + bv[ni].x, x3 = c[mi][ni][3] + bv[ni].y;
            if (OUT32) {
                float* C = (float*)Cout;
                *(float2*)&C[(size_t)r0 * N + col]       = make_float2(x0, x1);
                *(float2*)&C[(size_t)(r0 + 8) * N + col] = make_float2(x2, x3);
            } else {
                __half* C = (__half*)Cout;
                *(uint32_t*)&C[(size_t)r0 * N + col]       = pack_h2(x0, x1);
                *(uint32_t*)&C[(size_t)(r0 + 8) * N + col] = pack_h2(x2, x3);
            }
        }
    }
}

// ===========================================================================
// fp16 flash attention (R14 structure): O = softmax(QK^T/8)V per (b,h).
// 64-key tiles, 3-stage cp.async K/V ring (distance-2), one sync per iter.
// P stays in registers between QK and PV. Q also staged via cp.async so the
// first K/V fills overlap Q's load latency.
// ===========================================================================
#define KSTR 72
#define KVBUF (64 * KSTR)                 // halves per K (or V) buffer
#define ATT_SMEM ((3 * 2 * KVBUF + 128 * KSTR) * 2)   // 73728 bytes

__global__ __launch_bounds__(256, 2) void attn_f16_kernel()
{
    extern __shared__ __half sma[];
    const uint32_t sKbase = (uint32_t)__cvta_generic_to_shared(sma);
    const uint32_t sVbase = sKbase + (uint32_t)(3 * KVBUF) * 2;
    const uint32_t sQ     = sKbase + (uint32_t)(6 * KVBUF) * 2;

    const int t    = threadIdx.x;
    const int lane = t & 31;
    const int warp = t >> 5;
    const int grp  = lane >> 2;
    const int qid  = lane & 3;
    const int mm   = lane >> 3;
    const int rr   = lane & 7;

    const int bh = blockIdx.y;
    const int b  = bh >> 4;
    const int h  = bh & 15;
    const int hoff  = h * HDIM;
    const int qrow0 = blockIdx.x * 128;

    const int rowStride = QKV_COLS;
    const __half* Kg = g_qkv + (size_t)b * SEQ * rowStride + hoff;           // K third
    const __half* Vg = Kg + 2 * EMB;                                         // V third
    const __half* Qg = g_qkv + ((size_t)b * SEQ + qrow0) * rowStride + EMB + hoff;

    // K/V staging: 64 rows x 128B; 4 thr/row, 2x16B each
    const int kvrow = t >> 2;
    const int kvs0  = (t & 3) * 2;

    auto issue_kv = [&](int buf, int kt) {
        const __half* Kn = Kg + (size_t)kt * 64 * rowStride;
        const __half* Vn = Vg + (size_t)kt * 64 * rowStride;
        #pragma unroll
        for (int s = 0; s < 2; s++) {
            int seg = kvs0 + s;
            uint32_t off = (uint32_t)(buf * KVBUF + kvrow * KSTR + seg * 8) * 2;
            cp_async16(sKbase + off, Kn + (size_t)kvrow * rowStride + seg * 8);
            cp_async16(sVbase + off, Vn + (size_t)kvrow * rowStride + seg * 8);
        }
    };

    // prologue: K/V stage 0 first (overlaps Q staging latency)
    issue_kv(0, 0); cp_commit();

    // ---- stage Q via cp.async: 128 rows x 128B; 2 thr/row, 4x16B each ----
    {
        const int j  = t >> 1;
        const int s0 = (t & 1) * 4;
        const __half* Qr = Qg + (size_t)j * rowStride;
        #pragma unroll
        for (int p = 0; p < 4; p++) {
            int seg = s0 + p;
            cp_async16(sQ + (uint32_t)(j * KSTR + seg * 8) * 2, Qr + seg * 8);
        }
    }
    cp_commit();

    issue_kv(1, 1); cp_commit();

    // wait for K/V stage 0 + Q (2 newer groups outstanding: Q? no —
    // groups: [kv0][Q][kv1]; wait<1> leaves kv1 in flight, Q+kv0 done)
    cp_wait<1>();
    __syncthreads();

    // ---- Q fragments (held in registers) ----
    uint32_t qa[4][4];
    {
        const uint32_t qw = sQ +
            (uint32_t)((warp * 16 + rr + 8 * (mm & 1)) * KSTR + 8 * (mm >> 1)) * 2;
        #pragma unroll
        for (int ks = 0; ks < 4; ks++)
            ldsm_x4(qa[ks][0], qa[ks][1], qa[ks][2], qa[ks][3],
                    qw + (uint32_t)(ks * 16) * 2);
    }

    float oc[8][4];
    #pragma unroll
    for (int ni = 0; ni < 8; ni++)
        #pragma unroll
        for (int r = 0; r < 4; r++) oc[ni][r] = 0.0f;
    float lsum0 = 0.0f, lsum1 = 0.0f;

    const uint32_t kL = (uint32_t)((rr + 8 * (mm >> 1)) * KSTR + 8 * (mm & 1));
    const uint32_t vL = (uint32_t)((rr + 8 * (mm & 1)) * KSTR + 8 * (mm >> 1));

    const int NKT = SEQ / 64;   // 16
    for (int kt = 0; kt < NKT; kt++) {
        if (kt > 0) {           // stage kt must have landed
            if (kt + 2 < NKT) cp_wait<1>();
            else              cp_wait<0>();
            __syncthreads();
        }

        if (kt + 2 < NKT) {
            issue_kv((kt + 2) % 3, kt + 2);
            cp_commit();
        }

        const uint32_t sKb = sKbase + (uint32_t)((kt % 3) * KVBUF) * 2;
        const uint32_t sVb = sVbase + (uint32_t)((kt % 3) * KVBUF) * 2;

        // ---- S = Q K^T ----
        float sc[8][4];
        #pragma unroll
        for (int ni = 0; ni < 8; ni++)
            #pragma unroll
            for (int r = 0; r < 4; r++) sc[ni][r] = 0.0f;

        #pragma unroll
        for (int ks = 0; ks < 4; ks++) {
            uint32_t bf[8][2];
            #pragma unroll
            for (int ni2 = 0; ni2 < 4; ni2++)
                ldsm_x4(bf[2 * ni2][0], bf[2 * ni2][1],
                        bf[2 * ni2 + 1][0], bf[2 * ni2 + 1][1],
                        sKb + (uint32_t)(ni2 * 16 * KSTR + ks * 16 + kL) * 2);
            #pragma unroll
            for (int ni = 0; ni < 8; ni++)
                mma_f16(sc[ni], qa[ks], bf[ni]);
        }

        // ---- P = exp(S/8); row sums ----
        #pragma unroll
        for (int ni = 0; ni < 8; ni++) {
            sc[ni][0] = __expf(sc[ni][0] * 0.125f);
            sc[ni][1] = __expf(sc[ni][1] * 0.125f);
            sc[ni][2] = __expf(sc[ni][2] * 0.125f);
            sc[ni][3] = __expf(sc[ni][3] * 0.125f);
            lsum0 += sc[ni][0] + sc[ni][1];
            lsum1 += sc[ni][2] + sc[ni][3];
        }

        // ---- O += P V (P packed from registers; static ks) ----
        #pragma unroll
        for (int ks = 0; ks < 4; ks++) {
            uint32_t af[4];
            af[0] = pack_h2(sc[2 * ks][0],     sc[2 * ks][1]);
            af[1] = pack_h2(sc[2 * ks][2],     sc[2 * ks][3]);
            af[2] = pack_h2(sc[2 * ks + 1][0], sc[2 * ks + 1][1]);
            af[3] = pack_h2(sc[2 * ks + 1][2], sc[2 * ks + 1][3]);
            uint32_t bf[8][2];
            #pragma unroll
            for (int ni2 = 0; ni2 < 4; ni2++)
                ldsm_x4t(bf[2 * ni2][0], bf[2 * ni2][1],
                         bf[2 * ni2 + 1][0], bf[2 * ni2 + 1][1],
                         sVb + (uint32_t)(ks * 16 * KSTR + ni2 * 16 + vL) * 2);
            #pragma unroll
            for (int ni = 0; ni < 8; ni++)
                mma_f16(oc[ni], af, bf[ni]);
        }
        __syncthreads();   // all warps done with tile kt before refill of its slot
    }

    // ---- normalize, write fp16 ----
    float l0 = lsum0, l1 = lsum1;
    #pragma unroll
    for (int m = 1; m < 4; m <<= 1) {
        l0 += __shfl_xor_sync(0xffffffffu, l0, m);
        l1 += __shfl_xor_sync(0xffffffffu, l1, m);
    }
    const float inv0 = 1.0f / l0;
    const float inv1 = 1.0f / l1;

    const int r0 = qrow0 + warp * 16 + grp;
    __half* O0 = g_att + ((size_t)b * SEQ + r0) * EMB + hoff;
    __half* O1 = O0 + 8 * EMB;
    #pragma unroll
    for (int ni = 0; ni < 8; ni++) {
        const int col = ni * 8 + qid * 2;
        *(uint32_t*)&O0[col] = pack_h2(oc[ni][0] * inv0, oc[ni][1] * inv0);
        *(uint32_t*)&O1[col] = pack_h2(oc[ni][2] * inv1, oc[ni][3] * inv1);
    }
}

// ---------------------------------------------------------------------------
// Launch: inputs in order x, W_qkv, b_qkv, W_out, b_out
// ---------------------------------------------------------------------------
extern "C" void kernel_launch(void* const* d_in, const int* in_sizes, int n_in,
                              void* d_out, int out_size)
{
    const float* x     = (const float*)d_in[0];
    const float* W_qkv = (const float*)d_in[1];
    const float* b_qkv = (const float*)d_in[2];
    const float* W_out = (const float*)d_in[3];
    const float* b_out = (const float*)d_in[4];
    float*       out   = (float*)d_out;

    __half *qkv_p, *att_p, *xh_p, *wq_p, *wo_p;
    cudaGetSymbolAddress((void**)&qkv_p, g_qkv);
    cudaGetSymbolAddress((void**)&att_p, g_att);
    cudaGetSymbolAddress((void**)&xh_p,  g_xh);
    cudaGetSymbolAddress((void**)&wq_p,  g_wqkvh);
    cudaGetSymbolAddress((void**)&wo_p,  g_wouth);

    static bool attr_set = false;
    if (!attr_set) {
        cudaFuncSetAttribute(hgemm_bias<false>,
                             cudaFuncAttributeMaxDynamicSharedMemorySize, GEMM_SMEM);
        cudaFuncSetAttribute(hgemm_bias<true>,
                             cudaFuncAttributeMaxDynamicSharedMemorySize, GEMM_SMEM);
        cudaFuncSetAttribute(attn_f16_kernel,
                             cudaFuncAttributeMaxDynamicSharedMemorySize, ATT_SMEM);
        attr_set = true;
    }

    // 0) fp32 -> fp16 prepass (one launch for all three tensors)
    f2h3<<<1024, 256>>>(
        (const float2*)x,     (__half2*)xh_p, ROWS * EMB / 2,
        (const float2*)W_qkv, (__half2*)wq_p, EMB * QKV_COLS / 2,
        (const float2*)W_out, (__half2*)wo_p, EMB * EMB / 2);

    // 1) QKV projection -> fp16
    {
        dim3 grid(QKV_COLS / GBN, ROWS / GBM);   // (24, 32)
        hgemm_bias<false><<<grid, 256, GEMM_SMEM>>>(
            ROWS, QKV_COLS, EMB, xh_p, wq_p, b_qkv, qkv_p);
    }

    // 2) Attention -> fp16
    {
        dim3 grid(SEQ / 128, BATCH * NHEADS);    // (8, 64)
        attn_f16_kernel<<<grid, 256, ATT_SMEM>>>();
    }

    // 3) Output projection -> fp32
    {
        dim3 grid(EMB / GBN, ROWS / GBM);        // (8, 32)
        hgemm_bias<true><<<grid, 256, GEMM_SMEM>>>(
            ROWS, EMB, EMB, att_p, wo_p, b_out, out);
    }
}